// round 1
// baseline (speedup 1.0000x reference)
#include <cuda_runtime.h>
#include <math.h>

// Problem constants (fixed by the reference)
#define BATCH 2
#define SEQ   2048
#define DM    4096
#define NH    32
#define NKV   8
#define HDIM  128
#define MROWS (BATCH*SEQ)      // 4096 token rows
#define NREP  (NH/NKV)         // 4

// -------- static scratch (no allocations allowed) --------
static __device__ float g_q  [(size_t)MROWS*NH *HDIM];   // 64 MB
static __device__ float g_k  [(size_t)MROWS*NKV*HDIM];   // 16 MB
static __device__ float g_v  [(size_t)MROWS*NKV*HDIM];   // 16 MB
static __device__ float g_ctx[(size_t)MROWS*NH *HDIM];   // 64 MB

// ============================================================
// SGEMM: C[M,N] = A[M,K] @ B[K,N], all row-major fp32.
// 128x128 block tile, BK=8, 256 threads, 8x8 per-thread frag.
// M = gridDim.y*128; K,N multiples of 8/128 (true for all calls).
// ============================================================
__global__ __launch_bounds__(256) void sgemm128(const float* __restrict__ A,
                                                const float* __restrict__ B,
                                                float* __restrict__ C,
                                                int K, int N)
{
    __shared__ float As[8][128];
    __shared__ float Bs[8][128];

    const int t  = threadIdx.x;
    const int bm = blockIdx.y * 128;
    const int bn = blockIdx.x * 128;

    const int arow = t >> 1;            // 0..127
    const int acol = (t & 1) << 2;      // 0 or 4
    const int brow = t >> 5;            // 0..7
    const int bcol = (t & 31) << 2;     // 0..124

    const int ty = t >> 4;              // 0..15
    const int tx = t & 15;              // 0..15

    const float* Aptr = A + (size_t)(bm + arow) * K + acol;
    const float* Bptr = B + (size_t)brow * N + bn + bcol;

    float acc[8][8];
#pragma unroll
    for (int i = 0; i < 8; i++)
#pragma unroll
        for (int j = 0; j < 8; j++) acc[i][j] = 0.f;

    float4 a_nxt = *(const float4*)(Aptr);
    float4 b_nxt = *(const float4*)(Bptr);

    for (int k0 = 0; k0 < K; k0 += 8) {
        // stage current tile into smem
        As[acol + 0][arow] = a_nxt.x;
        As[acol + 1][arow] = a_nxt.y;
        As[acol + 2][arow] = a_nxt.z;
        As[acol + 3][arow] = a_nxt.w;
        *(float4*)&Bs[brow][bcol] = b_nxt;
        __syncthreads();

        // prefetch next tile (overlap with compute)
        if (k0 + 8 < K) {
            a_nxt = *(const float4*)(Aptr + (k0 + 8));
            b_nxt = *(const float4*)(Bptr + (size_t)(k0 + 8) * N);
        }

#pragma unroll
        for (int kk = 0; kk < 8; kk++) {
            float ar[8], br[8];
            *(float4*)&ar[0] = *(const float4*)&As[kk][ty * 4];
            *(float4*)&ar[4] = *(const float4*)&As[kk][64 + ty * 4];
            *(float4*)&br[0] = *(const float4*)&Bs[kk][tx * 4];
            *(float4*)&br[4] = *(const float4*)&Bs[kk][64 + tx * 4];
#pragma unroll
            for (int i = 0; i < 8; i++)
#pragma unroll
                for (int j = 0; j < 8; j++)
                    acc[i][j] = fmaf(ar[i], br[j], acc[i][j]);
        }
        __syncthreads();
    }

#pragma unroll
    for (int i = 0; i < 8; i++) {
        const int r = bm + ((i < 4) ? (ty * 4 + i) : (64 + ty * 4 + (i - 4)));
        float* Crow = C + (size_t)r * N + bn;
        *(float4*)&Crow[tx * 4]      = make_float4(acc[i][0], acc[i][1], acc[i][2], acc[i][3]);
        *(float4*)&Crow[64 + tx * 4] = make_float4(acc[i][4], acc[i][5], acc[i][6], acc[i][7]);
    }
}

// ============================================================
// RoPE (interleaved pairs, matching the reference):
//   x0 = x[2p], x1 = x[2p+1]; out[2p]=x0*c-x1*s; out[2p+1]=x0*s+x1*c
// Applied in-place to q [MROWS,NH,HD] and k [MROWS,NKV,HD].
// ============================================================
__global__ void rope_kernel(float* __restrict__ q, float* __restrict__ k,
                            const float* __restrict__ cosb,
                            const float* __restrict__ sinb)
{
    const int HALF = HDIM / 2;
    int idx = blockIdx.x * blockDim.x + threadIdx.x;
    const int total = MROWS * (NH + NKV) * HALF;
    if (idx >= total) return;

    const int p    = idx % HALF;
    int rest       = idx / HALF;
    const int hh   = rest % (NH + NKV);
    const int bs   = rest / (NH + NKV);     // b*SEQ + s
    const int s    = bs % SEQ;

    const float c  = cosb[s * HALF + p];
    const float sn = sinb[s * HALF + p];

    float2* ptr;
    if (hh < NH) ptr = (float2*)(q + ((size_t)bs * NH  + hh)        * HDIM) + p;
    else         ptr = (float2*)(k + ((size_t)bs * NKV + (hh - NH)) * HDIM) + p;

    float2 vv = *ptr;
    *ptr = make_float2(vv.x * c - vv.y * sn, vv.x * sn + vv.y * c);
}

// ============================================================
// Flash attention (causal, GQA), fp32, online softmax.
// Block: 256 threads, tile BM=64 q rows x BN=64 k cols, HD=128.
// Smem (dynamic, 84224 B): Qs[64][132] | KVs[64][132] | Ps[64][65]
// Thread (ty,tx) in 16x16: S rows m=ty+16i, cols n=tx+16j (i,j<4);
// O cols d = tx*4+j and 64+tx*4+j.
// ============================================================
#define FBM 64
#define FBN 64
#define QK_F4 33      // float4 row stride (132 floats) for Q/K/V tiles
#define PSTR  65      // float row stride for P tile
#define FLASH_SMEM ((2*FBM*132 + FBM*PSTR) * 4)   // 84224 bytes

__global__ __launch_bounds__(256) void flash_kernel(const float* __restrict__ q,
                                                    const float* __restrict__ k,
                                                    const float* __restrict__ v,
                                                    float* __restrict__ ctx)
{
    extern __shared__ float smf[];
    float* Qs  = smf;
    float* KVs = smf + FBM * 132;
    float* Ps  = smf + 2 * FBM * 132;

    const int t   = threadIdx.x;
    const int qt  = blockIdx.x;
    const int h   = blockIdx.y;
    const int b   = blockIdx.z;
    const int kvh = h / NREP;
    const int ty  = t >> 4;
    const int tx  = t & 15;
    const float scale = 0.08838834764831845f;  // 1/sqrt(128)

    // ---- load Q tile (scaled) ----
    {
        const float* qbase = q + (((size_t)(b * SEQ + qt * FBM)) * NH + h) * HDIM;
#pragma unroll
        for (int i = 0; i < 8; i++) {
            int idx = t + i * 256;          // 2048 float4 loads
            int row = idx >> 5, c4 = idx & 31;
            float4 val = *(const float4*)(qbase + (size_t)row * NH * HDIM + c4 * 4);
            val.x *= scale; val.y *= scale; val.z *= scale; val.w *= scale;
            *(float4*)&Qs[row * 132 + c4 * 4] = val;
        }
    }

    float m_i[4], l_i[4], o[4][8];
#pragma unroll
    for (int i = 0; i < 4; i++) {
        m_i[i] = -1e30f; l_i[i] = 0.f;
#pragma unroll
        for (int j = 0; j < 8; j++) o[i][j] = 0.f;
    }

    for (int kt = 0; kt <= qt; kt++) {
        __syncthreads();   // KVs free (prev PV done), Qs visible on first iter

        // ---- load K tile ----
        {
            const float* kbase = k + (((size_t)(b * SEQ + kt * FBN)) * NKV + kvh) * HDIM;
#pragma unroll
            for (int i = 0; i < 8; i++) {
                int idx = t + i * 256;
                int row = idx >> 5, c4 = idx & 31;
                *(float4*)&KVs[row * 132 + c4 * 4] =
                    *(const float4*)(kbase + (size_t)row * NKV * HDIM + c4 * 4);
            }
        }
        __syncthreads();

        // ---- S = Qs @ Ks^T fragment (4x4) ----
        float s_[4][4];
#pragma unroll
        for (int i = 0; i < 4; i++)
#pragma unroll
            for (int j = 0; j < 4; j++) s_[i][j] = 0.f;

        const float4* Q4 = (const float4*)Qs;
        const float4* K4 = (const float4*)KVs;
        for (int d4 = 0; d4 < 32; d4++) {
            float4 qv[4], kv[4];
#pragma unroll
            for (int i = 0; i < 4; i++) qv[i] = Q4[(ty + 16 * i) * QK_F4 + d4];
#pragma unroll
            for (int j = 0; j < 4; j++) kv[j] = K4[(tx + 16 * j) * QK_F4 + d4];
#pragma unroll
            for (int i = 0; i < 4; i++)
#pragma unroll
                for (int j = 0; j < 4; j++) {
                    s_[i][j] = fmaf(qv[i].x, kv[j].x, s_[i][j]);
                    s_[i][j] = fmaf(qv[i].y, kv[j].y, s_[i][j]);
                    s_[i][j] = fmaf(qv[i].z, kv[j].z, s_[i][j]);
                    s_[i][j] = fmaf(qv[i].w, kv[j].w, s_[i][j]);
                }
        }

        // ---- causal mask (diagonal block only) ----
        if (kt == qt) {
#pragma unroll
            for (int i = 0; i < 4; i++)
#pragma unroll
                for (int j = 0; j < 4; j++)
                    if ((tx + 16 * j) > (ty + 16 * i)) s_[i][j] = -1e30f;
        }

        // ---- online softmax stats + P + O rescale ----
#pragma unroll
        for (int i = 0; i < 4; i++) {
            float rmax = fmaxf(fmaxf(s_[i][0], s_[i][1]), fmaxf(s_[i][2], s_[i][3]));
#pragma unroll
            for (int off = 8; off >= 1; off >>= 1)
                rmax = fmaxf(rmax, __shfl_xor_sync(0xffffffffu, rmax, off));
            float mnew  = fmaxf(m_i[i], rmax);
            float alpha = __expf(m_i[i] - mnew);
            float rsum  = 0.f;
#pragma unroll
            for (int j = 0; j < 4; j++) {
                s_[i][j] = __expf(s_[i][j] - mnew);
                rsum += s_[i][j];
            }
#pragma unroll
            for (int off = 8; off >= 1; off >>= 1)
                rsum += __shfl_xor_sync(0xffffffffu, rsum, off);
            l_i[i] = l_i[i] * alpha + rsum;
            m_i[i] = mnew;
#pragma unroll
            for (int j = 0; j < 8; j++) o[i][j] *= alpha;
#pragma unroll
            for (int j = 0; j < 4; j++)
                Ps[(ty + 16 * i) * PSTR + tx + 16 * j] = s_[i][j];
        }
        __syncthreads();   // K reads + P writes done

        // ---- load V tile (reuse KVs) ----
        {
            const float* vbase = v + (((size_t)(b * SEQ + kt * FBN)) * NKV + kvh) * HDIM;
#pragma unroll
            for (int i = 0; i < 8; i++) {
                int idx = t + i * 256;
                int row = idx >> 5, c4 = idx & 31;
                *(float4*)&KVs[row * 132 + c4 * 4] =
                    *(const float4*)(vbase + (size_t)row * NKV * HDIM + c4 * 4);
            }
        }
        __syncthreads();

        // ---- O += P @ V ----
        const float4* V4 = (const float4*)KVs;
#pragma unroll 4
        for (int kk = 0; kk < FBN; kk++) {
            float4 v0 = V4[kk * QK_F4 + tx];
            float4 v1 = V4[kk * QK_F4 + 16 + tx];
#pragma unroll
            for (int i = 0; i < 4; i++) {
                float p = Ps[(ty + 16 * i) * PSTR + kk];
                o[i][0] = fmaf(p, v0.x, o[i][0]);
                o[i][1] = fmaf(p, v0.y, o[i][1]);
                o[i][2] = fmaf(p, v0.z, o[i][2]);
                o[i][3] = fmaf(p, v0.w, o[i][3]);
                o[i][4] = fmaf(p, v1.x, o[i][4]);
                o[i][5] = fmaf(p, v1.y, o[i][5]);
                o[i][6] = fmaf(p, v1.z, o[i][6]);
                o[i][7] = fmaf(p, v1.w, o[i][7]);
            }
        }
    }

    // ---- epilogue: normalize and store context ----
#pragma unroll
    for (int i = 0; i < 4; i++) {
        const float inv = 1.f / l_i[i];
        const int row = qt * FBM + ty + 16 * i;
        float* cb = ctx + (((size_t)(b * SEQ + row)) * NH + h) * HDIM;
        *(float4*)&cb[tx * 4] =
            make_float4(o[i][0] * inv, o[i][1] * inv, o[i][2] * inv, o[i][3] * inv);
        *(float4*)&cb[64 + tx * 4] =
            make_float4(o[i][4] * inv, o[i][5] * inv, o[i][6] * inv, o[i][7] * inv);
    }
}

// ============================================================
// Launch: x@wq, x@wk, x@wv -> rope -> flash -> ctx@wo
// Inputs: x, wq, wk, wv, wo, freqs_cos, freqs_sin, mask, start_pos
// (mask == causal -1e9 and start_pos == 0: folded into the flash kernel)
// ============================================================
extern "C" void kernel_launch(void* const* d_in, const int* in_sizes, int n_in,
                              void* d_out, int out_size)
{
    (void)in_sizes; (void)n_in; (void)out_size;
    const float* x  = (const float*)d_in[0];
    const float* wq = (const float*)d_in[1];
    const float* wk = (const float*)d_in[2];
    const float* wv = (const float*)d_in[3];
    const float* wo = (const float*)d_in[4];
    const float* fc = (const float*)d_in[5];
    const float* fs = (const float*)d_in[6];
    float* out = (float*)d_out;

    float *q, *k, *v, *ctx;
    cudaGetSymbolAddress((void**)&q,   g_q);
    cudaGetSymbolAddress((void**)&k,   g_k);
    cudaGetSymbolAddress((void**)&v,   g_v);
    cudaGetSymbolAddress((void**)&ctx, g_ctx);

    cudaFuncSetAttribute(flash_kernel,
                         cudaFuncAttributeMaxDynamicSharedMemorySize, FLASH_SMEM);

    // QKV projections
    sgemm128<<<dim3((NH  * HDIM) / 128, MROWS / 128), 256>>>(x, wq, q, DM, NH  * HDIM);
    sgemm128<<<dim3((NKV * HDIM) / 128, MROWS / 128), 256>>>(x, wk, k, DM, NKV * HDIM);
    sgemm128<<<dim3((NKV * HDIM) / 128, MROWS / 128), 256>>>(x, wv, v, DM, NKV * HDIM);

    // RoPE on q and k
    {
        const int total = MROWS * (NH + NKV) * (HDIM / 2);
        rope_kernel<<<(total + 255) / 256, 256>>>(q, k, fc, fs);
    }

    // causal GQA flash attention
    flash_kernel<<<dim3(SEQ / FBM, NH, BATCH), 256, FLASH_SMEM>>>(q, k, v, ctx);

    // output projection
    sgemm128<<<dim3(DM / 128, MROWS / 128), 256>>>(ctx, wo, out, NH * HDIM, DM);
}

// round 3
// speedup vs baseline: 1.6268x; 1.6268x over previous
#include <cuda_runtime.h>
#include <cuda_bf16.h>
#include <math.h>

// Problem constants (fixed by the reference)
#define BATCH 2
#define SEQ   2048
#define DM    4096
#define NH    32
#define NKV   8
#define HDIM  128
#define MROWS (BATCH*SEQ)      // 4096 token rows
#define NREP  (NH/NKV)         // 4

typedef unsigned int u32;
typedef unsigned short u16;

// -------- static scratch (no allocations allowed) --------
static __device__ float g_q  [(size_t)MROWS*NH *HDIM];   // 64 MB
static __device__ float g_k  [(size_t)MROWS*NKV*HDIM];   // 16 MB
static __device__ float g_v  [(size_t)MROWS*NKV*HDIM];   // 16 MB
static __device__ float g_ctx[(size_t)MROWS*NH *HDIM];   // 64 MB

// bf16 hi/lo splits of GEMM operands
static __device__ __nv_bfloat16 g_x_hi  [(size_t)MROWS*DM];
static __device__ __nv_bfloat16 g_x_lo  [(size_t)MROWS*DM];
static __device__ __nv_bfloat16 g_wq_hi [(size_t)DM*NH*HDIM];
static __device__ __nv_bfloat16 g_wq_lo [(size_t)DM*NH*HDIM];
static __device__ __nv_bfloat16 g_wk_hi [(size_t)DM*NKV*HDIM];
static __device__ __nv_bfloat16 g_wk_lo [(size_t)DM*NKV*HDIM];
static __device__ __nv_bfloat16 g_wv_hi [(size_t)DM*NKV*HDIM];
static __device__ __nv_bfloat16 g_wv_lo [(size_t)DM*NKV*HDIM];
static __device__ __nv_bfloat16 g_wo_hi [(size_t)NH*HDIM*DM];
static __device__ __nv_bfloat16 g_wo_lo [(size_t)NH*HDIM*DM];
static __device__ __nv_bfloat16 g_c_hi  [(size_t)MROWS*NH*HDIM];
static __device__ __nv_bfloat16 g_c_lo  [(size_t)MROWS*NH*HDIM];

// ============================================================
// split: x -> hi (bf16 rn) + lo (bf16 rn of residual)
// ============================================================
__global__ void split_kernel(const float* __restrict__ src,
                             __nv_bfloat16* __restrict__ hi,
                             __nv_bfloat16* __restrict__ lo, int n4)
{
    int i = blockIdx.x * blockDim.x + threadIdx.x;
    if (i >= n4) return;
    float4 v = ((const float4*)src)[i];
    __nv_bfloat16 h0 = __float2bfloat16_rn(v.x);
    __nv_bfloat16 h1 = __float2bfloat16_rn(v.y);
    __nv_bfloat16 h2 = __float2bfloat16_rn(v.z);
    __nv_bfloat16 h3 = __float2bfloat16_rn(v.w);
    __nv_bfloat16 l0 = __float2bfloat16_rn(v.x - __bfloat162float(h0));
    __nv_bfloat16 l1 = __float2bfloat16_rn(v.y - __bfloat162float(h1));
    __nv_bfloat16 l2 = __float2bfloat16_rn(v.z - __bfloat162float(h2));
    __nv_bfloat16 l3 = __float2bfloat16_rn(v.w - __bfloat162float(h3));
    __nv_bfloat162* H = (__nv_bfloat162*)hi;
    __nv_bfloat162* L = (__nv_bfloat162*)lo;
    H[2*i]   = __nv_bfloat162(h0, h1);
    H[2*i+1] = __nv_bfloat162(h2, h3);
    L[2*i]   = __nv_bfloat162(l0, l1);
    L[2*i+1] = __nv_bfloat162(l2, l3);
}

// ============================================================
// bf16x3 tensor-core GEMM: C[M,N] = (Ah+Al)[M,K] @ (Bh+Bl)[K,N]
//   C = Ah*Bh + Ah*Bl + Al*Bh   (fp32 accumulate, err ~2^-17)
// Block 128x128, BK=32, 256 thr (8 warps x 64x32), double-buffered,
// ONE barrier per K-tile (stores target the opposite stage whose
// readers all passed the previous barrier).
// ============================================================
#define GBK 32
#define A_ST 20              // u32 per A smem row (40 bf16, 32 used)
#define B_ST 136             // bf16 per B smem row (128 used)
#define A_SZ (128*A_ST)      // 2560 u32 per (hi|lo)
#define B_SZ (GBK*B_ST/2)    // 2176 u32 per (hi|lo)
#define STAGE_U32 (2*A_SZ + 2*B_SZ)        // 9472
#define GEMM_SMEM (2*STAGE_U32*4)          // 75776 bytes

__device__ __forceinline__ void mma_bf16(float* d, const u32* a, const u32* b)
{
    asm volatile(
        "mma.sync.aligned.m16n8k16.row.col.f32.bf16.bf16.f32 "
        "{%0,%1,%2,%3},{%4,%5,%6,%7},{%8,%9},{%0,%1,%2,%3};"
        : "+f"(d[0]), "+f"(d[1]), "+f"(d[2]), "+f"(d[3])
        : "r"(a[0]), "r"(a[1]), "r"(a[2]), "r"(a[3]), "r"(b[0]), "r"(b[1]));
}

__global__ __launch_bounds__(256, 1)
void gemm_bf16x3(const u16* __restrict__ Agh, const u16* __restrict__ Agl,
                 const u16* __restrict__ Bgh, const u16* __restrict__ Bgl,
                 float* __restrict__ C, int K, int N)
{
    extern __shared__ u32 sm[];
    const int t    = threadIdx.x;
    const int lane = t & 31;
    const int warp = t >> 5;
    const int bm   = blockIdx.y * 128;
    const int bn   = blockIdx.x * 128;
    const int g    = lane >> 2;      // 0..7
    const int t2   = lane & 3;       // 0..3
    const int m0   = (warp >> 2) * 64;
    const int n0   = (warp & 3) * 32;

    // gmem tile coords for the cooperative loads
    const int a_row = t >> 2;            // 0..63  (i adds +64)
    const int a_c8  = t & 3;             // 8-col group
    const int b_row = t >> 4;            // 0..15  (i adds +16)
    const int b_c8  = t & 15;

    float acc[4][4][4];
#pragma unroll
    for (int i = 0; i < 4; i++)
#pragma unroll
        for (int j = 0; j < 4; j++)
#pragma unroll
            for (int c = 0; c < 4; c++) acc[i][j][c] = 0.f;

    const int tiles = K / GBK;
    uint4 pah[2], pal[2], pbh[2], pbl[2];

#define LOADG(KT)                                                              \
    {                                                                          \
        const int kb = (KT) * GBK;                                             \
        _Pragma("unroll")                                                      \
        for (int i = 0; i < 2; i++) {                                          \
            size_t aoff = (size_t)(bm + a_row + i*64) * K + kb + a_c8*8;       \
            pah[i] = *(const uint4*)(Agh + aoff);                              \
            pal[i] = *(const uint4*)(Agl + aoff);                              \
            size_t boff = (size_t)(kb + b_row + i*16) * N + bn + b_c8*8;       \
            pbh[i] = *(const uint4*)(Bgh + boff);                              \
            pbl[i] = *(const uint4*)(Bgl + boff);                              \
        }                                                                      \
    }

#define STORES(ST)                                                             \
    {                                                                          \
        u32* base = sm + (ST) * STAGE_U32;                                     \
        _Pragma("unroll")                                                      \
        for (int i = 0; i < 2; i++) {                                          \
            *(uint4*)(base + (a_row + i*64)*A_ST + a_c8*4)        = pah[i];    \
            *(uint4*)(base + A_SZ + (a_row + i*64)*A_ST + a_c8*4) = pal[i];    \
            u16* bh16 = (u16*)(base + 2*A_SZ);                                 \
            u16* bl16 = (u16*)(base + 2*A_SZ + B_SZ);                          \
            *(uint4*)(bh16 + (b_row + i*16)*B_ST + b_c8*8) = pbh[i];           \
            *(uint4*)(bl16 + (b_row + i*16)*B_ST + b_c8*8) = pbl[i];           \
        }                                                                      \
    }

    LOADG(0);
    STORES(0);
    __syncthreads();

    for (int kt = 0; kt < tiles; kt++) {
        if (kt + 1 < tiles) LOADG(kt + 1);

        const u32* Ah = sm + (kt & 1) * STAGE_U32;
        const u32* Al = Ah + A_SZ;
        const u16* Bh = (const u16*)(Ah + 2*A_SZ);
        const u16* Bl = (const u16*)(Ah + 2*A_SZ + B_SZ);

#pragma unroll
        for (int ks = 0; ks < GBK; ks += 16) {
            u32 ah[4][4], al[4][4], bh[4][2], bl[4][2];
#pragma unroll
            for (int mt = 0; mt < 4; mt++) {
                const u32* ar = Ah + (m0 + mt*16 + g) * A_ST + (ks >> 1) + t2;
                ah[mt][0] = ar[0]; ah[mt][1] = ar[8*A_ST];
                ah[mt][2] = ar[4]; ah[mt][3] = ar[8*A_ST + 4];
                const u32* al_ = Al + (m0 + mt*16 + g) * A_ST + (ks >> 1) + t2;
                al[mt][0] = al_[0]; al[mt][1] = al_[8*A_ST];
                al[mt][2] = al_[4]; al[mt][3] = al_[8*A_ST + 4];
            }
#pragma unroll
            for (int nt = 0; nt < 4; nt++) {
                const int col = n0 + nt*8 + g;
                const u16* p = Bh + (ks + 2*t2) * B_ST + col;
                bh[nt][0] = (u32)p[0]       | ((u32)p[B_ST]     << 16);
                bh[nt][1] = (u32)p[8*B_ST]  | ((u32)p[9*B_ST]   << 16);
                const u16* q = Bl + (ks + 2*t2) * B_ST + col;
                bl[nt][0] = (u32)q[0]       | ((u32)q[B_ST]     << 16);
                bl[nt][1] = (u32)q[8*B_ST]  | ((u32)q[9*B_ST]   << 16);
            }
#pragma unroll
            for (int mt = 0; mt < 4; mt++)
#pragma unroll
                for (int nt = 0; nt < 4; nt++) {
                    mma_bf16(acc[mt][nt], ah[mt], bh[nt]);
                    mma_bf16(acc[mt][nt], ah[mt], bl[nt]);
                    mma_bf16(acc[mt][nt], al[mt], bh[nt]);
                }
        }

        // Write next tile into the opposite stage: its previous readers all
        // passed the barrier at the end of the prior iteration, so no WAR
        // hazard. One barrier per K-tile.
        if (kt + 1 < tiles) STORES((kt + 1) & 1);
        __syncthreads();
    }

    // epilogue: acc[mt][nt]{c0,c1}=row(m0+mt*16+g), cols 2t2,2t2+1; {c2,c3}=row+8
#pragma unroll
    for (int mt = 0; mt < 4; mt++)
#pragma unroll
        for (int nt = 0; nt < 4; nt++) {
            const int r0 = bm + m0 + mt*16 + g;
            const int c0 = bn + n0 + nt*8 + 2*t2;
            *(float2*)(C + (size_t)r0      * N + c0) = make_float2(acc[mt][nt][0], acc[mt][nt][1]);
            *(float2*)(C + (size_t)(r0+8)  * N + c0) = make_float2(acc[mt][nt][2], acc[mt][nt][3]);
        }
}

// ============================================================
// RoPE (interleaved pairs, matching the reference)
// ============================================================
__global__ void rope_kernel(float* __restrict__ q, float* __restrict__ k,
                            const float* __restrict__ cosb,
                            const float* __restrict__ sinb)
{
    const int HALF = HDIM / 2;
    int idx = blockIdx.x * blockDim.x + threadIdx.x;
    const int total = MROWS * (NH + NKV) * HALF;
    if (idx >= total) return;

    const int p    = idx % HALF;
    int rest       = idx / HALF;
    const int hh   = rest % (NH + NKV);
    const int bs   = rest / (NH + NKV);     // b*SEQ + s
    const int s    = bs % SEQ;

    const float c  = cosb[s * HALF + p];
    const float sn = sinb[s * HALF + p];

    float2* ptr;
    if (hh < NH) ptr = (float2*)(q + ((size_t)bs * NH  + hh)        * HDIM) + p;
    else         ptr = (float2*)(k + ((size_t)bs * NKV + (hh - NH)) * HDIM) + p;

    float2 vv = *ptr;
    *ptr = make_float2(vv.x * c - vv.y * sn, vv.x * sn + vv.y * c);
}

// ============================================================
// Flash attention (causal, GQA), fp32, online softmax.
// ============================================================
#define FBM 64
#define FBN 64
#define QK_F4 33
#define PSTR  65
#define FLASH_SMEM ((2*FBM*132 + FBM*PSTR) * 4)   // 84224 bytes

__global__ __launch_bounds__(256) void flash_kernel(const float* __restrict__ q,
                                                    const float* __restrict__ k,
                                                    const float* __restrict__ v,
                                                    float* __restrict__ ctx)
{
    extern __shared__ float smf[];
    float* Qs  = smf;
    float* KVs = smf + FBM * 132;
    float* Ps  = smf + 2 * FBM * 132;

    const int t   = threadIdx.x;
    const int qt  = blockIdx.x;
    const int h   = blockIdx.y;
    const int b   = blockIdx.z;
    const int kvh = h / NREP;
    const int ty  = t >> 4;
    const int tx  = t & 15;
    const float scale = 0.08838834764831845f;

    {
        const float* qbase = q + (((size_t)(b * SEQ + qt * FBM)) * NH + h) * HDIM;
#pragma unroll
        for (int i = 0; i < 8; i++) {
            int idx = t + i * 256;
            int row = idx >> 5, c4 = idx & 31;
            float4 val = *(const float4*)(qbase + (size_t)row * NH * HDIM + c4 * 4);
            val.x *= scale; val.y *= scale; val.z *= scale; val.w *= scale;
            *(float4*)&Qs[row * 132 + c4 * 4] = val;
        }
    }

    float m_i[4], l_i[4], o[4][8];
#pragma unroll
    for (int i = 0; i < 4; i++) {
        m_i[i] = -1e30f; l_i[i] = 0.f;
#pragma unroll
        for (int j = 0; j < 8; j++) o[i][j] = 0.f;
    }

    for (int kt = 0; kt <= qt; kt++) {
        __syncthreads();

        {
            const float* kbase = k + (((size_t)(b * SEQ + kt * FBN)) * NKV + kvh) * HDIM;
#pragma unroll
            for (int i = 0; i < 8; i++) {
                int idx = t + i * 256;
                int row = idx >> 5, c4 = idx & 31;
                *(float4*)&KVs[row * 132 + c4 * 4] =
                    *(const float4*)(kbase + (size_t)row * NKV * HDIM + c4 * 4);
            }
        }
        __syncthreads();

        float s_[4][4];
#pragma unroll
        for (int i = 0; i < 4; i++)
#pragma unroll
            for (int j = 0; j < 4; j++) s_[i][j] = 0.f;

        const float4* Q4 = (const float4*)Qs;
        const float4* K4 = (const float4*)KVs;
        for (int d4 = 0; d4 < 32; d4++) {
            float4 qv[4], kv[4];
#pragma unroll
            for (int i = 0; i < 4; i++) qv[i] = Q4[(ty + 16 * i) * QK_F4 + d4];
#pragma unroll
            for (int j = 0; j < 4; j++) kv[j] = K4[(tx + 16 * j) * QK_F4 + d4];
#pragma unroll
            for (int i = 0; i < 4; i++)
#pragma unroll
                for (int j = 0; j < 4; j++) {
                    s_[i][j] = fmaf(qv[i].x, kv[j].x, s_[i][j]);
                    s_[i][j] = fmaf(qv[i].y, kv[j].y, s_[i][j]);
                    s_[i][j] = fmaf(qv[i].z, kv[j].z, s_[i][j]);
                    s_[i][j] = fmaf(qv[i].w, kv[j].w, s_[i][j]);
                }
        }

        if (kt == qt) {
#pragma unroll
            for (int i = 0; i < 4; i++)
#pragma unroll
                for (int j = 0; j < 4; j++)
                    if ((tx + 16 * j) > (ty + 16 * i)) s_[i][j] = -1e30f;
        }

#pragma unroll
        for (int i = 0; i < 4; i++) {
            float rmax = fmaxf(fmaxf(s_[i][0], s_[i][1]), fmaxf(s_[i][2], s_[i][3]));
#pragma unroll
            for (int off = 8; off >= 1; off >>= 1)
                rmax = fmaxf(rmax, __shfl_xor_sync(0xffffffffu, rmax, off));
            float mnew  = fmaxf(m_i[i], rmax);
            float alpha = __expf(m_i[i] - mnew);
            float rsum  = 0.f;
#pragma unroll
            for (int j = 0; j < 4; j++) {
                s_[i][j] = __expf(s_[i][j] - mnew);
                rsum += s_[i][j];
            }
#pragma unroll
            for (int off = 8; off >= 1; off >>= 1)
                rsum += __shfl_xor_sync(0xffffffffu, rsum, off);
            l_i[i] = l_i[i] * alpha + rsum;
            m_i[i] = mnew;
#pragma unroll
            for (int j = 0; j < 8; j++) o[i][j] *= alpha;
#pragma unroll
            for (int j = 0; j < 4; j++)
                Ps[(ty + 16 * i) * PSTR + tx + 16 * j] = s_[i][j];
        }
        __syncthreads();

        {
            const float* vbase = v + (((size_t)(b * SEQ + kt * FBN)) * NKV + kvh) * HDIM;
#pragma unroll
            for (int i = 0; i < 8; i++) {
                int idx = t + i * 256;
                int row = idx >> 5, c4 = idx & 31;
                *(float4*)&KVs[row * 132 + c4 * 4] =
                    *(const float4*)(vbase + (size_t)row * NKV * HDIM + c4 * 4);
            }
        }
        __syncthreads();

        const float4* V4 = (const float4*)KVs;
#pragma unroll 4
        for (int kk = 0; kk < FBN; kk++) {
            float4 v0 = V4[kk * QK_F4 + tx];
            float4 v1 = V4[kk * QK_F4 + 16 + tx];
#pragma unroll
            for (int i = 0; i < 4; i++) {
                float p = Ps[(ty + 16 * i) * PSTR + kk];
                o[i][0] = fmaf(p, v0.x, o[i][0]);
                o[i][1] = fmaf(p, v0.y, o[i][1]);
                o[i][2] = fmaf(p, v0.z, o[i][2]);
                o[i][3] = fmaf(p, v0.w, o[i][3]);
                o[i][4] = fmaf(p, v1.x, o[i][4]);
                o[i][5] = fmaf(p, v1.y, o[i][5]);
                o[i][6] = fmaf(p, v1.z, o[i][6]);
                o[i][7] = fmaf(p, v1.w, o[i][7]);
            }
        }
    }

#pragma unroll
    for (int i = 0; i < 4; i++) {
        const float inv = 1.f / l_i[i];
        const int row = qt * FBM + ty + 16 * i;
        float* cb = ctx + (((size_t)(b * SEQ + row)) * NH + h) * HDIM;
        *(float4*)&cb[tx * 4] =
            make_float4(o[i][0] * inv, o[i][1] * inv, o[i][2] * inv, o[i][3] * inv);
        *(float4*)&cb[64 + tx * 4] =
            make_float4(o[i][4] * inv, o[i][5] * inv, o[i][6] * inv, o[i][7] * inv);
    }
}

// ============================================================
// Launch graph
// ============================================================
extern "C" void kernel_launch(void* const* d_in, const int* in_sizes, int n_in,
                              void* d_out, int out_size)
{
    (void)in_sizes; (void)n_in; (void)out_size;
    const float* x  = (const float*)d_in[0];
    const float* wq = (const float*)d_in[1];
    const float* wk = (const float*)d_in[2];
    const float* wv = (const float*)d_in[3];
    const float* wo = (const float*)d_in[4];
    const float* fc = (const float*)d_in[5];
    const float* fs = (const float*)d_in[6];
    float* out = (float*)d_out;

    float *q, *k, *v, *ctx;
    cudaGetSymbolAddress((void**)&q,   g_q);
    cudaGetSymbolAddress((void**)&k,   g_k);
    cudaGetSymbolAddress((void**)&v,   g_v);
    cudaGetSymbolAddress((void**)&ctx, g_ctx);

    __nv_bfloat16 *xh, *xl, *wqh, *wql, *wkh, *wkl, *wvh, *wvl, *woh, *wol, *ch, *cl;
    cudaGetSymbolAddress((void**)&xh,  g_x_hi);  cudaGetSymbolAddress((void**)&xl,  g_x_lo);
    cudaGetSymbolAddress((void**)&wqh, g_wq_hi); cudaGetSymbolAddress((void**)&wql, g_wq_lo);
    cudaGetSymbolAddress((void**)&wkh, g_wk_hi); cudaGetSymbolAddress((void**)&wkl, g_wk_lo);
    cudaGetSymbolAddress((void**)&wvh, g_wv_hi); cudaGetSymbolAddress((void**)&wvl, g_wv_lo);
    cudaGetSymbolAddress((void**)&woh, g_wo_hi); cudaGetSymbolAddress((void**)&wol, g_wo_lo);
    cudaGetSymbolAddress((void**)&ch,  g_c_hi);  cudaGetSymbolAddress((void**)&cl,  g_c_lo);

    cudaFuncSetAttribute(flash_kernel,
                         cudaFuncAttributeMaxDynamicSharedMemorySize, FLASH_SMEM);
    cudaFuncSetAttribute(gemm_bf16x3,
                         cudaFuncAttributeMaxDynamicSharedMemorySize, GEMM_SMEM);

    // split fp32 operands into bf16 hi/lo
    {
        int n4;
        n4 = (MROWS*DM)/4;        split_kernel<<<(n4+255)/256,256>>>(x,  xh,  xl,  n4);
        n4 = (DM*NH*HDIM)/4;      split_kernel<<<(n4+255)/256,256>>>(wq, wqh, wql, n4);
        n4 = (DM*NKV*HDIM)/4;     split_kernel<<<(n4+255)/256,256>>>(wk, wkh, wkl, n4);
        n4 = (DM*NKV*HDIM)/4;     split_kernel<<<(n4+255)/256,256>>>(wv, wvh, wvl, n4);
        n4 = (NH*HDIM*DM)/4;      split_kernel<<<(n4+255)/256,256>>>(wo, woh, wol, n4);
    }

    // QKV projections (tensor core bf16x3)
    gemm_bf16x3<<<dim3((NH *HDIM)/128, MROWS/128), 256, GEMM_SMEM>>>(
        (const u16*)xh, (const u16*)xl, (const u16*)wqh, (const u16*)wql, q, DM, NH*HDIM);
    gemm_bf16x3<<<dim3((NKV*HDIM)/128, MROWS/128), 256, GEMM_SMEM>>>(
        (const u16*)xh, (const u16*)xl, (const u16*)wkh, (const u16*)wkl, k, DM, NKV*HDIM);
    gemm_bf16x3<<<dim3((NKV*HDIM)/128, MROWS/128), 256, GEMM_SMEM>>>(
        (const u16*)xh, (const u16*)xl, (const u16*)wvh, (const u16*)wvl, v, DM, NKV*HDIM);

    // RoPE on q and k
    {
        const int total = MROWS * (NH + NKV) * (HDIM / 2);
        rope_kernel<<<(total + 255) / 256, 256>>>(q, k, fc, fs);
    }

    // causal GQA flash attention (fp32)
    flash_kernel<<<dim3(SEQ / FBM, NH, BATCH), 256, FLASH_SMEM>>>(q, k, v, ctx);

    // split ctx, then output projection (tensor core bf16x3)
    {
        int n4 = (MROWS*NH*HDIM)/4;
        split_kernel<<<(n4+255)/256,256>>>(ctx, ch, cl, n4);
    }
    gemm_bf16x3<<<dim3(DM/128, MROWS/128), 256, GEMM_SMEM>>>(
        (const u16*)ch, (const u16*)cl, (const u16*)woh, (const u16*)wol, out, NH*HDIM, DM);
}

// round 4
// speedup vs baseline: 2.0949x; 1.2877x over previous
#include <cuda_runtime.h>
#include <cuda_bf16.h>
#include <math.h>

// Problem constants (fixed by the reference)
#define BATCH 2
#define SEQ   2048
#define DM    4096
#define NH    32
#define NKV   8
#define HDIM  128
#define MROWS (BATCH*SEQ)      // 4096 token rows
#define NREP  (NH/NKV)         // 4

typedef unsigned int u32;
typedef unsigned short u16;

// -------- static scratch (no allocations allowed) --------
static __device__ float g_q  [(size_t)MROWS*NH *HDIM];   // fp32 gemm out (pre-rope)
static __device__ float g_k  [(size_t)MROWS*NKV*HDIM];
static __device__ float g_v  [(size_t)MROWS*NKV*HDIM];

// bf16 hi/lo splits
static __device__ __nv_bfloat16 g_x_hi  [(size_t)MROWS*DM];
static __device__ __nv_bfloat16 g_x_lo  [(size_t)MROWS*DM];
static __device__ __nv_bfloat16 g_wq_hi [(size_t)DM*NH*HDIM];
static __device__ __nv_bfloat16 g_wq_lo [(size_t)DM*NH*HDIM];
static __device__ __nv_bfloat16 g_wk_hi [(size_t)DM*NKV*HDIM];
static __device__ __nv_bfloat16 g_wk_lo [(size_t)DM*NKV*HDIM];
static __device__ __nv_bfloat16 g_wv_hi [(size_t)DM*NKV*HDIM];
static __device__ __nv_bfloat16 g_wv_lo [(size_t)DM*NKV*HDIM];
static __device__ __nv_bfloat16 g_wo_hi [(size_t)NH*HDIM*DM];
static __device__ __nv_bfloat16 g_wo_lo [(size_t)NH*HDIM*DM];
static __device__ __nv_bfloat16 g_c_hi  [(size_t)MROWS*NH*HDIM];
static __device__ __nv_bfloat16 g_c_lo  [(size_t)MROWS*NH*HDIM];
// post-rope q/k and v in bf16 hi/lo for the mma flash kernel
static __device__ __nv_bfloat16 g_qh [(size_t)MROWS*NH *HDIM];
static __device__ __nv_bfloat16 g_ql [(size_t)MROWS*NH *HDIM];
static __device__ __nv_bfloat16 g_kh [(size_t)MROWS*NKV*HDIM];
static __device__ __nv_bfloat16 g_kl [(size_t)MROWS*NKV*HDIM];
static __device__ __nv_bfloat16 g_vh [(size_t)MROWS*NKV*HDIM];
static __device__ __nv_bfloat16 g_vl [(size_t)MROWS*NKV*HDIM];

// pack two floats into bf16x2 hi + bf16x2 residual
__device__ __forceinline__ void packsplit2(float a, float b, u32& hi, u32& lo)
{
    __nv_bfloat162 h = __floats2bfloat162_rn(a, b);
    __nv_bfloat162 l = __floats2bfloat162_rn(a - __low2float(h), b - __high2float(h));
    hi = *reinterpret_cast<u32*>(&h);
    lo = *reinterpret_cast<u32*>(&l);
}

// ============================================================
// split: x -> hi (bf16 rn) + lo (bf16 rn of residual)
// ============================================================
__global__ void split_kernel(const float* __restrict__ src,
                             __nv_bfloat16* __restrict__ hi,
                             __nv_bfloat16* __restrict__ lo, int n4)
{
    int i = blockIdx.x * blockDim.x + threadIdx.x;
    if (i >= n4) return;
    float4 v = ((const float4*)src)[i];
    u32 h0, l0, h1, l1;
    packsplit2(v.x, v.y, h0, l0);
    packsplit2(v.z, v.w, h1, l1);
    ((u32*)hi)[2*i]   = h0;  ((u32*)hi)[2*i+1] = h1;
    ((u32*)lo)[2*i]   = l0;  ((u32*)lo)[2*i+1] = l1;
}

// ============================================================
// bf16x3 tensor-core GEMM (validated R3): C = Ah*Bh + Ah*Bl + Al*Bh
// ============================================================
#define GBK 32
#define A_ST 20
#define B_ST 136
#define A_SZ (128*A_ST)
#define B_SZ (GBK*B_ST/2)
#define STAGE_U32 (2*A_SZ + 2*B_SZ)
#define GEMM_SMEM (2*STAGE_U32*4)

__device__ __forceinline__ void mma_bf16(float* d, const u32* a, const u32* b)
{
    asm volatile(
        "mma.sync.aligned.m16n8k16.row.col.f32.bf16.bf16.f32 "
        "{%0,%1,%2,%3},{%4,%5,%6,%7},{%8,%9},{%0,%1,%2,%3};"
        : "+f"(d[0]), "+f"(d[1]), "+f"(d[2]), "+f"(d[3])
        : "r"(a[0]), "r"(a[1]), "r"(a[2]), "r"(a[3]), "r"(b[0]), "r"(b[1]));
}

__global__ __launch_bounds__(256, 1)
void gemm_bf16x3(const u16* __restrict__ Agh, const u16* __restrict__ Agl,
                 const u16* __restrict__ Bgh, const u16* __restrict__ Bgl,
                 float* __restrict__ C, int K, int N)
{
    extern __shared__ u32 sm[];
    const int t    = threadIdx.x;
    const int lane = t & 31;
    const int warp = t >> 5;
    const int bm   = blockIdx.y * 128;
    const int bn   = blockIdx.x * 128;
    const int g    = lane >> 2;
    const int t2   = lane & 3;
    const int m0   = (warp >> 2) * 64;
    const int n0   = (warp & 3) * 32;

    const int a_row = t >> 2;
    const int a_c8  = t & 3;
    const int b_row = t >> 4;
    const int b_c8  = t & 15;

    float acc[4][4][4];
#pragma unroll
    for (int i = 0; i < 4; i++)
#pragma unroll
        for (int j = 0; j < 4; j++)
#pragma unroll
            for (int c = 0; c < 4; c++) acc[i][j][c] = 0.f;

    const int tiles = K / GBK;
    uint4 pah[2], pal[2], pbh[2], pbl[2];

#define LOADG(KT)                                                              \
    {                                                                          \
        const int kb = (KT) * GBK;                                             \
        _Pragma("unroll")                                                      \
        for (int i = 0; i < 2; i++) {                                          \
            size_t aoff = (size_t)(bm + a_row + i*64) * K + kb + a_c8*8;       \
            pah[i] = *(const uint4*)(Agh + aoff);                              \
            pal[i] = *(const uint4*)(Agl + aoff);                              \
            size_t boff = (size_t)(kb + b_row + i*16) * N + bn + b_c8*8;       \
            pbh[i] = *(const uint4*)(Bgh + boff);                              \
            pbl[i] = *(const uint4*)(Bgl + boff);                              \
        }                                                                      \
    }

#define STORES(ST)                                                             \
    {                                                                          \
        u32* base = sm + (ST) * STAGE_U32;                                     \
        _Pragma("unroll")                                                      \
        for (int i = 0; i < 2; i++) {                                          \
            *(uint4*)(base + (a_row + i*64)*A_ST + a_c8*4)        = pah[i];    \
            *(uint4*)(base + A_SZ + (a_row + i*64)*A_ST + a_c8*4) = pal[i];    \
            u16* bh16 = (u16*)(base + 2*A_SZ);                                 \
            u16* bl16 = (u16*)(base + 2*A_SZ + B_SZ);                          \
            *(uint4*)(bh16 + (b_row + i*16)*B_ST + b_c8*8) = pbh[i];           \
            *(uint4*)(bl16 + (b_row + i*16)*B_ST + b_c8*8) = pbl[i];           \
        }                                                                      \
    }

    LOADG(0);
    STORES(0);
    __syncthreads();

    for (int kt = 0; kt < tiles; kt++) {
        if (kt + 1 < tiles) LOADG(kt + 1);

        const u32* Ah = sm + (kt & 1) * STAGE_U32;
        const u32* Al = Ah + A_SZ;
        const u16* Bh = (const u16*)(Ah + 2*A_SZ);
        const u16* Bl = (const u16*)(Ah + 2*A_SZ + B_SZ);

#pragma unroll
        for (int ks = 0; ks < GBK; ks += 16) {
            u32 ah[4][4], al[4][4], bh[4][2], bl[4][2];
#pragma unroll
            for (int mt = 0; mt < 4; mt++) {
                const u32* ar = Ah + (m0 + mt*16 + g) * A_ST + (ks >> 1) + t2;
                ah[mt][0] = ar[0]; ah[mt][1] = ar[8*A_ST];
                ah[mt][2] = ar[4]; ah[mt][3] = ar[8*A_ST + 4];
                const u32* al_ = Al + (m0 + mt*16 + g) * A_ST + (ks >> 1) + t2;
                al[mt][0] = al_[0]; al[mt][1] = al_[8*A_ST];
                al[mt][2] = al_[4]; al[mt][3] = al_[8*A_ST + 4];
            }
#pragma unroll
            for (int nt = 0; nt < 4; nt++) {
                const int col = n0 + nt*8 + g;
                const u16* p = Bh + (ks + 2*t2) * B_ST + col;
                bh[nt][0] = (u32)p[0]       | ((u32)p[B_ST]     << 16);
                bh[nt][1] = (u32)p[8*B_ST]  | ((u32)p[9*B_ST]   << 16);
                const u16* q = Bl + (ks + 2*t2) * B_ST + col;
                bl[nt][0] = (u32)q[0]       | ((u32)q[B_ST]     << 16);
                bl[nt][1] = (u32)q[8*B_ST]  | ((u32)q[9*B_ST]   << 16);
            }
#pragma unroll
            for (int mt = 0; mt < 4; mt++)
#pragma unroll
                for (int nt = 0; nt < 4; nt++) {
                    mma_bf16(acc[mt][nt], ah[mt], bh[nt]);
                    mma_bf16(acc[mt][nt], ah[mt], bl[nt]);
                    mma_bf16(acc[mt][nt], al[mt], bh[nt]);
                }
        }

        if (kt + 1 < tiles) STORES((kt + 1) & 1);
        __syncthreads();
    }

#pragma unroll
    for (int mt = 0; mt < 4; mt++)
#pragma unroll
        for (int nt = 0; nt < 4; nt++) {
            const int r0 = bm + m0 + mt*16 + g;
            const int c0 = bn + n0 + nt*8 + 2*t2;
            *(float2*)(C + (size_t)r0      * N + c0) = make_float2(acc[mt][nt][0], acc[mt][nt][1]);
            *(float2*)(C + (size_t)(r0+8)  * N + c0) = make_float2(acc[mt][nt][2], acc[mt][nt][3]);
        }
}

// ============================================================
// RoPE + scale(q) + bf16 hi/lo split. Reads fp32 gemm outputs,
// writes bf16 hi/lo arrays for the mma flash kernel.
// ============================================================
__global__ void rope_split_kernel(const float* __restrict__ q,
                                  const float* __restrict__ k,
                                  const float* __restrict__ cosb,
                                  const float* __restrict__ sinb,
                                  __nv_bfloat16* __restrict__ qh,
                                  __nv_bfloat16* __restrict__ ql,
                                  __nv_bfloat16* __restrict__ kh,
                                  __nv_bfloat16* __restrict__ kl)
{
    const int HALF = HDIM / 2;
    const float scale = 0.08838834764831845f;   // 1/sqrt(128)
    int idx = blockIdx.x * blockDim.x + threadIdx.x;
    const int total = MROWS * (NH + NKV) * HALF;
    if (idx >= total) return;

    const int p    = idx % HALF;
    int rest       = idx / HALF;
    const int hh   = rest % (NH + NKV);
    const int bs   = rest / (NH + NKV);
    const int s    = bs % SEQ;

    const float c  = cosb[s * HALF + p];
    const float sn = sinb[s * HALF + p];

    if (hh < NH) {
        size_t off = ((size_t)bs * NH + hh) * HDIM;
        float2 vv = *((const float2*)(q + off) + p);
        float o0 = (vv.x * c - vv.y * sn) * scale;
        float o1 = (vv.x * sn + vv.y * c) * scale;
        u32 hv, lv;
        packsplit2(o0, o1, hv, lv);
        ((u32*)(qh + off))[p] = hv;
        ((u32*)(ql + off))[p] = lv;
    } else {
        size_t off = ((size_t)bs * NKV + (hh - NH)) * HDIM;
        float2 vv = *((const float2*)(k + off) + p);
        float o0 = vv.x * c - vv.y * sn;
        float o1 = vv.x * sn + vv.y * c;
        u32 hv, lv;
        packsplit2(o0, o1, hv, lv);
        ((u32*)(kh + off))[p] = hv;
        ((u32*)(kl + off))[p] = lv;
    }
}

// ============================================================
// Tensor-core flash attention (causal, GQA), bf16x3, online softmax.
// Block: 128 threads (4 warps). Tile: BM=64 q rows x BN=64 keys, HD=128.
// Warp w owns rows 16w..16w+15. S accs: 8 n8-tiles; O accs: 16 n8-tiles.
// P passes register-to-register from S accums into the PV mma (FA2-style).
// Smem: Qh|Ql|Kh|Kl|Vh|Vl, each 64 rows x 136 bf16 (stride 68 u32).
// ============================================================
#define FROW32 68                        // u32 per smem row (136 bf16)
#define FTILE (64*FROW32)                // 4352 u32 per tile
#define FLASH_SMEM (6*FTILE*4)           // 104448 bytes

__global__ __launch_bounds__(128, 2)
void flash_mma_kernel(const u16* __restrict__ qh, const u16* __restrict__ ql,
                      const u16* __restrict__ kh, const u16* __restrict__ kl,
                      const u16* __restrict__ vh, const u16* __restrict__ vl,
                      u32* __restrict__ ch, u32* __restrict__ cl)
{
    extern __shared__ u32 fsm[];
    u32* Qh = fsm;
    u32* Ql = fsm + FTILE;
    u32* Kh = fsm + 2*FTILE;
    u32* Kl = fsm + 3*FTILE;
    u32* Vh = fsm + 4*FTILE;
    u32* Vl = fsm + 5*FTILE;

    const int t    = threadIdx.x;
    const int lane = t & 31;
    const int w    = t >> 5;
    const int g    = lane >> 2;     // 0..7
    const int t2   = lane & 3;      // 0..3
    const int qt   = blockIdx.x;
    const int h    = blockIdx.y;
    const int b    = blockIdx.z;
    const int kvh  = h / NREP;

    // ---- load Q tile (hi/lo) ----
#pragma unroll
    for (int i = 0; i < 8; i++) {
        int idx = t + i * 128;
        int row = idx >> 4, c8 = idx & 15;
        size_t go = ((size_t)(b * SEQ + qt * 64 + row) * NH + h) * HDIM + c8 * 8;
        *(uint4*)(Qh + row * FROW32 + c8 * 4) = *(const uint4*)(qh + go);
        *(uint4*)(Ql + row * FROW32 + c8 * 4) = *(const uint4*)(ql + go);
    }

    float o[16][4];
#pragma unroll
    for (int jj = 0; jj < 16; jj++)
#pragma unroll
        for (int c = 0; c < 4; c++) o[jj][c] = 0.f;
    float m0 = -1e30f, m1 = -1e30f, l0 = 0.f, l1 = 0.f;

    const int r0loc = w * 16 + g;       // local q row (and +8)

    for (int kt = 0; kt <= qt; kt++) {
        // ---- load K,V tiles (hi/lo) ----
#pragma unroll
        for (int i = 0; i < 8; i++) {
            int idx = t + i * 128;
            int row = idx >> 4, c8 = idx & 15;
            size_t go = ((size_t)(b * SEQ + kt * 64 + row) * NKV + kvh) * HDIM + c8 * 8;
            *(uint4*)(Kh + row * FROW32 + c8 * 4) = *(const uint4*)(kh + go);
            *(uint4*)(Kl + row * FROW32 + c8 * 4) = *(const uint4*)(kl + go);
            *(uint4*)(Vh + row * FROW32 + c8 * 4) = *(const uint4*)(vh + go);
            *(uint4*)(Vl + row * FROW32 + c8 * 4) = *(const uint4*)(vl + go);
        }
        __syncthreads();

        // ---- S = Q K^T (bf16x3) ----
        float sacc[8][4];
#pragma unroll
        for (int j = 0; j < 8; j++)
#pragma unroll
            for (int c = 0; c < 4; c++) sacc[j][c] = 0.f;

#pragma unroll
        for (int ks = 0; ks < 8; ks++) {
            u32 qa[4], qb[4];
            const u32* qr = Qh + r0loc * FROW32 + 8 * ks + t2;
            qa[0] = qr[0]; qa[1] = qr[8 * FROW32];
            qa[2] = qr[4]; qa[3] = qr[8 * FROW32 + 4];
            const u32* qr2 = Ql + r0loc * FROW32 + 8 * ks + t2;
            qb[0] = qr2[0]; qb[1] = qr2[8 * FROW32];
            qb[2] = qr2[4]; qb[3] = qr2[8 * FROW32 + 4];
#pragma unroll
            for (int j = 0; j < 8; j++) {
                u32 bh_[2], bl_[2];
                const u32* kr = Kh + (8 * j + g) * FROW32 + 8 * ks + t2;
                bh_[0] = kr[0]; bh_[1] = kr[4];
                const u32* kr2 = Kl + (8 * j + g) * FROW32 + 8 * ks + t2;
                bl_[0] = kr2[0]; bl_[1] = kr2[4];
                mma_bf16(sacc[j], qa, bh_);
                mma_bf16(sacc[j], qa, bl_);
                mma_bf16(sacc[j], qb, bh_);
            }
        }

        // ---- causal mask on diagonal tile ----
        if (kt == qt) {
#pragma unroll
            for (int j = 0; j < 8; j++) {
                int c0 = 8 * j + 2 * t2;
                if (c0     > r0loc)     sacc[j][0] = -1e30f;
                if (c0 + 1 > r0loc)     sacc[j][1] = -1e30f;
                if (c0     > r0loc + 8) sacc[j][2] = -1e30f;
                if (c0 + 1 > r0loc + 8) sacc[j][3] = -1e30f;
            }
        }

        // ---- online softmax (rows g and g+8 of this warp) ----
        float rmax0 = -1e30f, rmax1 = -1e30f;
#pragma unroll
        for (int j = 0; j < 8; j++) {
            rmax0 = fmaxf(rmax0, fmaxf(sacc[j][0], sacc[j][1]));
            rmax1 = fmaxf(rmax1, fmaxf(sacc[j][2], sacc[j][3]));
        }
        rmax0 = fmaxf(rmax0, __shfl_xor_sync(0xffffffffu, rmax0, 1));
        rmax0 = fmaxf(rmax0, __shfl_xor_sync(0xffffffffu, rmax0, 2));
        rmax1 = fmaxf(rmax1, __shfl_xor_sync(0xffffffffu, rmax1, 1));
        rmax1 = fmaxf(rmax1, __shfl_xor_sync(0xffffffffu, rmax1, 2));

        float mn0 = fmaxf(m0, rmax0);
        float mn1 = fmaxf(m1, rmax1);
        float a0  = __expf(m0 - mn0);
        float a1  = __expf(m1 - mn1);
        m0 = mn0; m1 = mn1;

        float rs0 = 0.f, rs1 = 0.f;
#pragma unroll
        for (int j = 0; j < 8; j++) {
            sacc[j][0] = __expf(sacc[j][0] - mn0);
            sacc[j][1] = __expf(sacc[j][1] - mn0);
            sacc[j][2] = __expf(sacc[j][2] - mn1);
            sacc[j][3] = __expf(sacc[j][3] - mn1);
            rs0 += sacc[j][0] + sacc[j][1];
            rs1 += sacc[j][2] + sacc[j][3];
        }
        rs0 += __shfl_xor_sync(0xffffffffu, rs0, 1);
        rs0 += __shfl_xor_sync(0xffffffffu, rs0, 2);
        rs1 += __shfl_xor_sync(0xffffffffu, rs1, 1);
        rs1 += __shfl_xor_sync(0xffffffffu, rs1, 2);
        l0 = l0 * a0 + rs0;
        l1 = l1 * a1 + rs1;

#pragma unroll
        for (int jj = 0; jj < 16; jj++) {
            o[jj][0] *= a0; o[jj][1] *= a0;
            o[jj][2] *= a1; o[jj][3] *= a1;
        }

        // ---- O += P V (bf16x3, P from registers) ----
#pragma unroll
        for (int s = 0; s < 4; s++) {
            u32 pa[4], pb[4];
            packsplit2(sacc[2*s  ][0], sacc[2*s  ][1], pa[0], pb[0]);
            packsplit2(sacc[2*s  ][2], sacc[2*s  ][3], pa[1], pb[1]);
            packsplit2(sacc[2*s+1][0], sacc[2*s+1][1], pa[2], pb[2]);
            packsplit2(sacc[2*s+1][2], sacc[2*s+1][3], pa[3], pb[3]);
#pragma unroll
            for (int jj = 0; jj < 16; jj++) {
                u32 bh_[2], bl_[2];
                const u16* vb = (const u16*)Vh + (16*s + 2*t2) * 136 + 8*jj + g;
                bh_[0] = (u32)vb[0]       | ((u32)vb[136]   << 16);
                bh_[1] = (u32)vb[8*136]   | ((u32)vb[9*136] << 16);
                const u16* vb2 = (const u16*)Vl + (16*s + 2*t2) * 136 + 8*jj + g;
                bl_[0] = (u32)vb2[0]      | ((u32)vb2[136]   << 16);
                bl_[1] = (u32)vb2[8*136]  | ((u32)vb2[9*136] << 16);
                mma_bf16(o[jj], pa, bh_);
                mma_bf16(o[jj], pa, bl_);
                mma_bf16(o[jj], pb, bh_);
            }
        }
        __syncthreads();   // all K/V reads done before next tile overwrite
    }

    // ---- epilogue: normalize, split to bf16 hi/lo, store ----
    const float inv0 = 1.f / l0;
    const float inv1 = 1.f / l1;
    const size_t row0 = (size_t)(b * SEQ + qt * 64 + r0loc);
    const size_t cbase = (size_t)h * HDIM;
#pragma unroll
    for (int jj = 0; jj < 16; jj++) {
        int d0 = 8 * jj + 2 * t2;
        u32 hv, lv;
        size_t i0 = (row0 * (NH * HDIM) + cbase + d0) >> 1;
        packsplit2(o[jj][0] * inv0, o[jj][1] * inv0, hv, lv);
        ch[i0] = hv; cl[i0] = lv;
        size_t i1 = ((row0 + 8) * (NH * HDIM) + cbase + d0) >> 1;
        packsplit2(o[jj][2] * inv1, o[jj][3] * inv1, hv, lv);
        ch[i1] = hv; cl[i1] = lv;
    }
}

// ============================================================
// Launch graph
// ============================================================
extern "C" void kernel_launch(void* const* d_in, const int* in_sizes, int n_in,
                              void* d_out, int out_size)
{
    (void)in_sizes; (void)n_in; (void)out_size;
    const float* x  = (const float*)d_in[0];
    const float* wq = (const float*)d_in[1];
    const float* wk = (const float*)d_in[2];
    const float* wv = (const float*)d_in[3];
    const float* wo = (const float*)d_in[4];
    const float* fc = (const float*)d_in[5];
    const float* fs = (const float*)d_in[6];
    float* out = (float*)d_out;

    float *q, *k, *v;
    cudaGetSymbolAddress((void**)&q, g_q);
    cudaGetSymbolAddress((void**)&k, g_k);
    cudaGetSymbolAddress((void**)&v, g_v);

    __nv_bfloat16 *xh, *xl, *wqh, *wql, *wkh, *wkl, *wvh, *wvl, *woh, *wol, *chb, *clb;
    __nv_bfloat16 *qhb, *qlb, *khb, *klb, *vhb, *vlb;
    cudaGetSymbolAddress((void**)&xh,  g_x_hi);  cudaGetSymbolAddress((void**)&xl,  g_x_lo);
    cudaGetSymbolAddress((void**)&wqh, g_wq_hi); cudaGetSymbolAddress((void**)&wql, g_wq_lo);
    cudaGetSymbolAddress((void**)&wkh, g_wk_hi); cudaGetSymbolAddress((void**)&wkl, g_wk_lo);
    cudaGetSymbolAddress((void**)&wvh, g_wv_hi); cudaGetSymbolAddress((void**)&wvl, g_wv_lo);
    cudaGetSymbolAddress((void**)&woh, g_wo_hi); cudaGetSymbolAddress((void**)&wol, g_wo_lo);
    cudaGetSymbolAddress((void**)&chb, g_c_hi);  cudaGetSymbolAddress((void**)&clb, g_c_lo);
    cudaGetSymbolAddress((void**)&qhb, g_qh);    cudaGetSymbolAddress((void**)&qlb, g_ql);
    cudaGetSymbolAddress((void**)&khb, g_kh);    cudaGetSymbolAddress((void**)&klb, g_kl);
    cudaGetSymbolAddress((void**)&vhb, g_vh);    cudaGetSymbolAddress((void**)&vlb, g_vl);

    cudaFuncSetAttribute(gemm_bf16x3,
                         cudaFuncAttributeMaxDynamicSharedMemorySize, GEMM_SMEM);
    cudaFuncSetAttribute(flash_mma_kernel,
                         cudaFuncAttributeMaxDynamicSharedMemorySize, FLASH_SMEM);

    // split fp32 operands into bf16 hi/lo
    {
        int n4;
        n4 = (MROWS*DM)/4;        split_kernel<<<(n4+255)/256,256>>>(x,  xh,  xl,  n4);
        n4 = (DM*NH*HDIM)/4;      split_kernel<<<(n4+255)/256,256>>>(wq, wqh, wql, n4);
        n4 = (DM*NKV*HDIM)/4;     split_kernel<<<(n4+255)/256,256>>>(wk, wkh, wkl, n4);
        n4 = (DM*NKV*HDIM)/4;     split_kernel<<<(n4+255)/256,256>>>(wv, wvh, wvl, n4);
        n4 = (NH*HDIM*DM)/4;      split_kernel<<<(n4+255)/256,256>>>(wo, woh, wol, n4);
    }

    // QKV projections (tensor core bf16x3)
    gemm_bf16x3<<<dim3((NH *HDIM)/128, MROWS/128), 256, GEMM_SMEM>>>(
        (const u16*)xh, (const u16*)xl, (const u16*)wqh, (const u16*)wql, q, DM, NH*HDIM);
    gemm_bf16x3<<<dim3((NKV*HDIM)/128, MROWS/128), 256, GEMM_SMEM>>>(
        (const u16*)xh, (const u16*)xl, (const u16*)wkh, (const u16*)wkl, k, DM, NKV*HDIM);
    gemm_bf16x3<<<dim3((NKV*HDIM)/128, MROWS/128), 256, GEMM_SMEM>>>(
        (const u16*)xh, (const u16*)xl, (const u16*)wvh, (const u16*)wvl, v, DM, NKV*HDIM);

    // RoPE + scale + split q/k; split v
    {
        const int total = MROWS * (NH + NKV) * (HDIM / 2);
        rope_split_kernel<<<(total + 255) / 256, 256>>>(q, k, fc, fs,
                                                        qhb, qlb, khb, klb);
        int n4 = (MROWS*NKV*HDIM)/4;
        split_kernel<<<(n4+255)/256,256>>>(v, vhb, vlb, n4);
    }

    // causal GQA flash attention (tensor core bf16x3)
    flash_mma_kernel<<<dim3(SEQ/64, NH, BATCH), 128, FLASH_SMEM>>>(
        (const u16*)qhb, (const u16*)qlb, (const u16*)khb, (const u16*)klb,
        (const u16*)vhb, (const u16*)vlb, (u32*)chb, (u32*)clb);

    // output projection (tensor core bf16x3)
    gemm_bf16x3<<<dim3(DM/128, MROWS/128), 256, GEMM_SMEM>>>(
        (const u16*)chb, (const u16*)clb, (const u16*)woh, (const u16*)wol, out, NH*HDIM, DM);
}